// round 1
// baseline (speedup 1.0000x reference)
#include <cuda_runtime.h>

#define DIM 1024
#define NH 16
#define HD 64
#define BATCH 2
#define SEQ 2048
#define MROWS (BATCH*SEQ)   // 4096

// Scratch (allocation-free rule: __device__ globals)
__device__ float g_q[BATCH*NH*SEQ*HD];    // [b][h][l][hd]
__device__ float g_k[BATCH*NH*SEQ*HD];
__device__ float g_v[BATCH*NH*SEQ*HD];
__device__ float g_ctx[MROWS*DIM];        // [b*l][d]

// ---------------------------------------------------------------------------
// Tiled fp32 GEMM: out[M,N] = A[M,K] @ W[K,N] + bias  (M=4096, N=K=1024)
// BM=BN=64, BK=16, 256 threads, 4x4 micro-tile per thread.
// scatter=1: write into [b][h][l][hd] layout (for Q/K/V).
// ---------------------------------------------------------------------------
__global__ __launch_bounds__(256) void gemm64(
    const float* __restrict__ A, const float* __restrict__ W,
    const float* __restrict__ bias, float* __restrict__ out, int scatter)
{
    __shared__ float As[16][64];   // [k][m] (transposed)
    __shared__ float Bs[16][64];   // [k][n]

    const int t  = threadIdx.x;
    const int tx = t & 15, ty = t >> 4;
    const int m0 = blockIdx.y << 6, n0 = blockIdx.x << 6;
    const int ar = t >> 2, ak = (t & 3) << 2;   // A tile: 64 rows x 4 float4
    const int bk = t >> 4, bn = (t & 15) << 2;  // B tile: 16 rows x 16 float4

    float acc[4][4] = {};

    for (int k0 = 0; k0 < DIM; k0 += 16) {
        float4 av = *(const float4*)&A[(size_t)(m0 + ar) * DIM + k0 + ak];
        float4 bv = *(const float4*)&W[(size_t)(k0 + bk) * DIM + n0 + bn];
        As[ak + 0][ar] = av.x; As[ak + 1][ar] = av.y;
        As[ak + 2][ar] = av.z; As[ak + 3][ar] = av.w;
        *(float4*)&Bs[bk][bn] = bv;
        __syncthreads();

        #pragma unroll
        for (int k = 0; k < 16; k++) {
            float4 a4 = *(const float4*)&As[k][ty << 2];
            float4 b4 = *(const float4*)&Bs[k][tx << 2];
            float a[4] = {a4.x, a4.y, a4.z, a4.w};
            float b[4] = {b4.x, b4.y, b4.z, b4.w};
            #pragma unroll
            for (int i = 0; i < 4; i++)
                #pragma unroll
                for (int j = 0; j < 4; j++)
                    acc[i][j] += a[i] * b[j];
        }
        __syncthreads();
    }

    #pragma unroll
    for (int i = 0; i < 4; i++) {
        int row = m0 + (ty << 2) + i;
        float4 o;
        o.x = acc[i][0] + bias[n0 + (tx << 2) + 0];
        o.y = acc[i][1] + bias[n0 + (tx << 2) + 1];
        o.z = acc[i][2] + bias[n0 + (tx << 2) + 2];
        o.w = acc[i][3] + bias[n0 + (tx << 2) + 3];
        if (scatter) {
            int b = row >> 11, l = row & 2047;
            int h = n0 >> 6;                 // BN=64 == head dim -> one head/block
            int dd = tx << 2;
            *(float4*)&out[((size_t)((b * NH + h) * SEQ) + l) * HD + dd] = o;
        } else {
            *(float4*)&out[(size_t)row * DIM + n0 + (tx << 2)] = o;
        }
    }
}

// ---------------------------------------------------------------------------
// Flash attention with quiet softmax (denominator = 1 + sum exp) and causal
// mask. One block per (q-tile of 64, b*h). 256 threads, 4x4 register tiles
// for both S = Q K^T and O += P V.
// Dynamic smem: Qt[64][64] (k-major), Kt[64][64] (k-major), Vs[64][64],
// Ps[64][64] = 64 KB.
// ---------------------------------------------------------------------------
__global__ __launch_bounds__(256) void attn_kernel(
    const float* __restrict__ gq, const float* __restrict__ gk,
    const float* __restrict__ gv, float* __restrict__ ctx)
{
    extern __shared__ float sm[];
    float* Qt = sm;            // Qt[k*64 + r]
    float* Kt = sm + 4096;     // Kt[k*64 + c]
    float* Vs = sm + 8192;     // Vs[c*64 + d]
    float* Ps = sm + 12288;    // Ps[r*64 + c]

    const int t  = threadIdx.x;
    const int tx = t & 15, ty = t >> 4;
    const int bh = blockIdx.y;
    const int q0 = blockIdx.x << 6;

    const float* Q = gq + (size_t)bh * SEQ * HD;
    const float* K = gk + (size_t)bh * SEQ * HD;
    const float* V = gv + (size_t)bh * SEQ * HD;

    // Load Q tile transposed into Qt[k][r]
    #pragma unroll
    for (int i = 0; i < 4; i++) {
        int f = t + (i << 8);
        int r = f >> 4, c4 = (f & 15) << 2;
        float4 v = *(const float4*)&Q[(size_t)(q0 + r) * HD + c4];
        Qt[(c4 + 0) * 64 + r] = v.x; Qt[(c4 + 1) * 64 + r] = v.y;
        Qt[(c4 + 2) * 64 + r] = v.z; Qt[(c4 + 3) * 64 + r] = v.w;
    }

    float m[4], lsum[4], o[4][4];
    #pragma unroll
    for (int i = 0; i < 4; i++) {
        m[i] = -1e30f; lsum[i] = 0.f;
        #pragma unroll
        for (int j = 0; j < 4; j++) o[i][j] = 0.f;
    }

    const int ktmax = blockIdx.x;   // causal: only tiles with k0 <= q0+63
    for (int kt = 0; kt <= ktmax; kt++) {
        const int k0 = kt << 6;

        // Load K tile (transposed) and V tile (row-major)
        #pragma unroll
        for (int i = 0; i < 4; i++) {
            int f = t + (i << 8);
            int r = f >> 4, c4 = (f & 15) << 2;
            float4 kv = *(const float4*)&K[(size_t)(k0 + r) * HD + c4];
            Kt[(c4 + 0) * 64 + r] = kv.x; Kt[(c4 + 1) * 64 + r] = kv.y;
            Kt[(c4 + 2) * 64 + r] = kv.z; Kt[(c4 + 3) * 64 + r] = kv.w;
            *(float4*)&Vs[r * 64 + c4] = *(const float4*)&V[(size_t)(k0 + r) * HD + c4];
        }
        __syncthreads();

        // S = Q K^T * (1/sqrt(64))
        float s[4][4] = {};
        #pragma unroll 8
        for (int k = 0; k < 64; k++) {
            float4 a4 = *(const float4*)&Qt[k * 64 + (ty << 2)];
            float4 b4 = *(const float4*)&Kt[k * 64 + (tx << 2)];
            float a[4] = {a4.x, a4.y, a4.z, a4.w};
            float b[4] = {b4.x, b4.y, b4.z, b4.w};
            #pragma unroll
            for (int i = 0; i < 4; i++)
                #pragma unroll
                for (int j = 0; j < 4; j++)
                    s[i][j] += a[i] * b[j];
        }
        #pragma unroll
        for (int i = 0; i < 4; i++)
            #pragma unroll
            for (int j = 0; j < 4; j++)
                s[i][j] *= 0.125f;

        // Causal mask (only the diagonal tile needs it)
        if (kt == ktmax) {
            #pragma unroll
            for (int i = 0; i < 4; i++)
                #pragma unroll
                for (int j = 0; j < 4; j++)
                    if (k0 + (tx << 2) + j > q0 + (ty << 2) + i)
                        s[i][j] = -1e30f;
        }

        // Online quiet softmax update per row
        #pragma unroll
        for (int i = 0; i < 4; i++) {
            float rm = fmaxf(fmaxf(s[i][0], s[i][1]), fmaxf(s[i][2], s[i][3]));
            rm = fmaxf(rm, __shfl_xor_sync(0xffffffffu, rm, 8));
            rm = fmaxf(rm, __shfl_xor_sync(0xffffffffu, rm, 4));
            rm = fmaxf(rm, __shfl_xor_sync(0xffffffffu, rm, 2));
            rm = fmaxf(rm, __shfl_xor_sync(0xffffffffu, rm, 1));
            float mn = fmaxf(m[i], rm);
            float al = __expf(m[i] - mn);
            float ls = 0.f;
            #pragma unroll
            for (int j = 0; j < 4; j++) {
                s[i][j] = __expf(s[i][j] - mn);
                ls += s[i][j];
            }
            ls += __shfl_xor_sync(0xffffffffu, ls, 8);
            ls += __shfl_xor_sync(0xffffffffu, ls, 4);
            ls += __shfl_xor_sync(0xffffffffu, ls, 2);
            ls += __shfl_xor_sync(0xffffffffu, ls, 1);
            lsum[i] = lsum[i] * al + ls;
            m[i] = mn;
            #pragma unroll
            for (int j = 0; j < 4; j++) o[i][j] *= al;
            // Store P row-major (float4, conflict-free)
            float4 pv = {s[i][0], s[i][1], s[i][2], s[i][3]};
            *(float4*)&Ps[((ty << 2) + i) * 64 + (tx << 2)] = pv;
        }
        __syncthreads();

        // O += P @ V
        #pragma unroll 4
        for (int c = 0; c < 64; c++) {
            float4 b4 = *(const float4*)&Vs[c * 64 + (tx << 2)];
            #pragma unroll
            for (int i = 0; i < 4; i++) {
                float a = Ps[((ty << 2) + i) * 64 + c];
                o[i][0] += a * b4.x; o[i][1] += a * b4.y;
                o[i][2] += a * b4.z; o[i][3] += a * b4.w;
            }
        }
        __syncthreads();   // before next tile overwrites Kt/Vs
    }

    // Epilogue: divide by (1 + l), write ctx in [b*l][d] layout
    const int b = bh >> 4, h = bh & 15;
    #pragma unroll
    for (int i = 0; i < 4; i++) {
        int row = q0 + (ty << 2) + i;
        float inv = 1.0f / (1.0f + lsum[i]);
        float4 ov = {o[i][0] * inv, o[i][1] * inv, o[i][2] * inv, o[i][3] * inv};
        *(float4*)&ctx[((size_t)(b * SEQ + row)) * DIM + h * HD + (tx << 2)] = ov;
    }
}

// ---------------------------------------------------------------------------
extern "C" void kernel_launch(void* const* d_in, const int* in_sizes, int n_in,
                              void* d_out, int out_size)
{
    const float* x  = (const float*)d_in[0];
    const float* Wq = (const float*)d_in[1];
    const float* bq = (const float*)d_in[2];
    const float* Wk = (const float*)d_in[3];
    const float* bk = (const float*)d_in[4];
    const float* Wv = (const float*)d_in[5];
    const float* bv = (const float*)d_in[6];
    const float* Wo = (const float*)d_in[7];
    const float* bo = (const float*)d_in[8];

    float *q, *k, *v, *ctx;
    cudaGetSymbolAddress((void**)&q,   g_q);
    cudaGetSymbolAddress((void**)&k,   g_k);
    cudaGetSymbolAddress((void**)&v,   g_v);
    cudaGetSymbolAddress((void**)&ctx, g_ctx);

    cudaFuncSetAttribute(attn_kernel,
                         cudaFuncAttributeMaxDynamicSharedMemorySize, 65536);

    dim3 gg(DIM / 64, MROWS / 64);   // (16, 64)
    gemm64<<<gg, 256>>>(x, Wq, bq, q, 1);
    gemm64<<<gg, 256>>>(x, Wk, bk, k, 1);
    gemm64<<<gg, 256>>>(x, Wv, bv, v, 1);
    attn_kernel<<<dim3(SEQ / 64, BATCH * NH), 256, 65536>>>(q, k, v, ctx);
    gemm64<<<gg, 256>>>(ctx, Wo, bo, (float*)d_out, 0);
}

// round 5
// speedup vs baseline: 1.7926x; 1.7926x over previous
#include <cuda_runtime.h>
#include <cstdint>

#define DIM 1024
#define NH 16
#define HD 64
#define BATCH 2
#define SEQ 2048
#define MROWS (BATCH*SEQ)   // 4096

// Scratch (allocation-free rule: __device__ globals)
__device__ float g_q[BATCH*NH*SEQ*HD];    // [b][h][l][hd]
__device__ float g_k[BATCH*NH*SEQ*HD];
__device__ float g_v[BATCH*NH*SEQ*HD];
__device__ float g_ctx[MROWS*DIM];        // [b*l][d]

__device__ __forceinline__ float to_tf32(float x) {
    float r;
    asm("cvt.rna.tf32.f32 %0, %1;" : "=f"(r) : "f"(x));
    return r;
}

__device__ __forceinline__ void mma_tf32(float d[4],
                                         uint32_t a0, uint32_t a1, uint32_t a2, uint32_t a3,
                                         uint32_t b0, uint32_t b1) {
    asm volatile(
        "mma.sync.aligned.m16n8k8.row.col.f32.tf32.tf32.f32 "
        "{%0,%1,%2,%3}, {%4,%5,%6,%7}, {%8,%9}, {%0,%1,%2,%3};"
        : "+f"(d[0]), "+f"(d[1]), "+f"(d[2]), "+f"(d[3])
        : "r"(a0), "r"(a1), "r"(a2), "r"(a3), "r"(b0), "r"(b1));
}

// ---------------------------------------------------------------------------
// tf32 tensor-core GEMM: out[M,N] = A[M,K] @ W[K,N] + bias
// M=4096, N=K=1024. BM=128, BN=128, BK=16. 256 threads = 8 warps,
// warp grid 2(m) x 4(n), warp tile 64x32, mma m16n8k8: 4x4 tiles per k8.
// Smem stride 136 floats => fragment LDS bank = 8*t4 + g (conflict-free).
// scatter=1: write into [b][h][l][hd] layout (for Q/K/V).
// ---------------------------------------------------------------------------
#define SST 136
__global__ __launch_bounds__(256) void gemm_tf32(
    const float* __restrict__ A, const float* __restrict__ W,
    const float* __restrict__ bias, float* __restrict__ out, int scatter)
{
    __shared__ float As[16 * SST];   // [k][m], m in 0..127
    __shared__ float Bs[16 * SST];   // [k][n], n in 0..127

    const int t    = threadIdx.x;
    const int warp = t >> 5, lane = t & 31;
    const int g  = lane >> 2;      // groupID 0..7
    const int t4 = lane & 3;       // threadID_in_group 0..3
    const int wm = (warp >> 2) << 6;   // 0 or 64
    const int wn = (warp & 3) << 5;    // 0,32,64,96
    const int m0 = blockIdx.y << 7, n0 = blockIdx.x << 7;

    float acc[4][4][4];
    #pragma unroll
    for (int mi = 0; mi < 4; mi++)
        #pragma unroll
        for (int ni = 0; ni < 4; ni++)
            #pragma unroll
            for (int e = 0; e < 4; e++) acc[mi][ni][e] = 0.f;

    for (int k0 = 0; k0 < DIM; k0 += 16) {
        // Stage A tile: rows m0..m0+127, cols k0..k0+15 -> As[k][m] (transposed)
        #pragma unroll
        for (int i = 0; i < 2; i++) {
            int f = t + (i << 8);
            int r = f >> 2, kc = (f & 3) << 2;
            float4 v = *(const float4*)&A[(size_t)(m0 + r) * DIM + k0 + kc];
            As[(kc + 0) * SST + r] = to_tf32(v.x);
            As[(kc + 1) * SST + r] = to_tf32(v.y);
            As[(kc + 2) * SST + r] = to_tf32(v.z);
            As[(kc + 3) * SST + r] = to_tf32(v.w);
        }
        // Stage B tile: rows k0..k0+15, cols n0..n0+127 -> Bs[k][n]
        #pragma unroll
        for (int i = 0; i < 2; i++) {
            int f = t + (i << 8);
            int kr = f >> 5, nc = (f & 31) << 2;
            float4 v = *(const float4*)&W[(size_t)(k0 + kr) * DIM + n0 + nc];
            float4 c;
            c.x = to_tf32(v.x); c.y = to_tf32(v.y);
            c.z = to_tf32(v.z); c.w = to_tf32(v.w);
            *(float4*)&Bs[kr * SST + nc] = c;
        }
        __syncthreads();

        #pragma unroll
        for (int kk = 0; kk < 16; kk += 8) {
            uint32_t aF[4][4], bF[4][2];
            #pragma unroll
            for (int mi = 0; mi < 4; mi++) {
                int m = wm + (mi << 4);
                aF[mi][0] = __float_as_uint(As[(kk + t4) * SST + m + g]);
                aF[mi][1] = __float_as_uint(As[(kk + t4) * SST + m + g + 8]);
                aF[mi][2] = __float_as_uint(As[(kk + t4 + 4) * SST + m + g]);
                aF[mi][3] = __float_as_uint(As[(kk + t4 + 4) * SST + m + g + 8]);
            }
            #pragma unroll
            for (int ni = 0; ni < 4; ni++) {
                int n = wn + (ni << 3) + g;
                bF[ni][0] = __float_as_uint(Bs[(kk + t4) * SST + n]);
                bF[ni][1] = __float_as_uint(Bs[(kk + t4 + 4) * SST + n]);
            }
            #pragma unroll
            for (int mi = 0; mi < 4; mi++)
                #pragma unroll
                for (int ni = 0; ni < 4; ni++)
                    mma_tf32(acc[mi][ni], aF[mi][0], aF[mi][1], aF[mi][2], aF[mi][3],
                             bF[ni][0], bF[ni][1]);
        }
        __syncthreads();
    }

    // Epilogue: acc[mi][ni] covers rows {r0, r0+8}, cols {c0, c0+1}
    #pragma unroll
    for (int mi = 0; mi < 4; mi++) {
        #pragma unroll
        for (int ni = 0; ni < 4; ni++) {
            int r0 = m0 + wm + (mi << 4) + g;
            int c0 = n0 + wn + (ni << 3) + (t4 << 1);
            float bx = bias[c0], by = bias[c0 + 1];
            #pragma unroll
            for (int half = 0; half < 2; half++) {
                int row = r0 + (half << 3);
                float2 o;
                o.x = acc[mi][ni][half * 2 + 0] + bx;
                o.y = acc[mi][ni][half * 2 + 1] + by;
                if (scatter) {
                    int b = row >> 11, l = row & 2047;
                    int h = c0 >> 6, dd = c0 & 63;
                    *(float2*)&out[((size_t)((b * NH + h) * SEQ) + l) * HD + dd] = o;
                } else {
                    *(float2*)&out[(size_t)row * DIM + c0] = o;
                }
            }
        }
    }
}

// ---------------------------------------------------------------------------
// Flash attention with quiet softmax (denominator = 1 + sum exp) and causal
// mask. One block per (q-tile of 64, b*h). 256 threads, 4x4 register tiles.
// (unchanged from R1 — known correct; mma conversion next round)
// ---------------------------------------------------------------------------
__global__ __launch_bounds__(256) void attn_kernel(
    const float* __restrict__ gq, const float* __restrict__ gk,
    const float* __restrict__ gv, float* __restrict__ ctx)
{
    extern __shared__ float sm[];
    float* Qt = sm;            // Qt[k*64 + r]
    float* Kt = sm + 4096;     // Kt[k*64 + c]
    float* Vs = sm + 8192;     // Vs[c*64 + d]
    float* Ps = sm + 12288;    // Ps[r*64 + c]

    const int t  = threadIdx.x;
    const int tx = t & 15, ty = t >> 4;
    const int bh = blockIdx.y;
    const int q0 = blockIdx.x << 6;

    const float* Q = gq + (size_t)bh * SEQ * HD;
    const float* K = gk + (size_t)bh * SEQ * HD;
    const float* V = gv + (size_t)bh * SEQ * HD;

    #pragma unroll
    for (int i = 0; i < 4; i++) {
        int f = t + (i << 8);
        int r = f >> 4, c4 = (f & 15) << 2;
        float4 v = *(const float4*)&Q[(size_t)(q0 + r) * HD + c4];
        Qt[(c4 + 0) * 64 + r] = v.x; Qt[(c4 + 1) * 64 + r] = v.y;
        Qt[(c4 + 2) * 64 + r] = v.z; Qt[(c4 + 3) * 64 + r] = v.w;
    }

    float m[4], lsum[4], o[4][4];
    #pragma unroll
    for (int i = 0; i < 4; i++) {
        m[i] = -1e30f; lsum[i] = 0.f;
        #pragma unroll
        for (int j = 0; j < 4; j++) o[i][j] = 0.f;
    }

    const int ktmax = blockIdx.x;
    for (int kt = 0; kt <= ktmax; kt++) {
        const int k0 = kt << 6;

        #pragma unroll
        for (int i = 0; i < 4; i++) {
            int f = t + (i << 8);
            int r = f >> 4, c4 = (f & 15) << 2;
            float4 kv = *(const float4*)&K[(size_t)(k0 + r) * HD + c4];
            Kt[(c4 + 0) * 64 + r] = kv.x; Kt[(c4 + 1) * 64 + r] = kv.y;
            Kt[(c4 + 2) * 64 + r] = kv.z; Kt[(c4 + 3) * 64 + r] = kv.w;
            *(float4*)&Vs[r * 64 + c4] = *(const float4*)&V[(size_t)(k0 + r) * HD + c4];
        }
        __syncthreads();

        float s[4][4] = {};
        #pragma unroll 8
        for (int k = 0; k < 64; k++) {
            float4 a4 = *(const float4*)&Qt[k * 64 + (ty << 2)];
            float4 b4 = *(const float4*)&Kt[k * 64 + (tx << 2)];
            float a[4] = {a4.x, a4.y, a4.z, a4.w};
            float b[4] = {b4.x, b4.y, b4.z, b4.w};
            #pragma unroll
            for (int i = 0; i < 4; i++)
                #pragma unroll
                for (int j = 0; j < 4; j++)
                    s[i][j] += a[i] * b[j];
        }
        #pragma unroll
        for (int i = 0; i < 4; i++)
            #pragma unroll
            for (int j = 0; j < 4; j++)
                s[i][j] *= 0.125f;

        if (kt == ktmax) {
            #pragma unroll
            for (int i = 0; i < 4; i++)
                #pragma unroll
                for (int j = 0; j < 4; j++)
                    if (k0 + (tx << 2) + j > q0 + (ty << 2) + i)
                        s[i][j] = -1e30f;
        }

        #pragma unroll
        for (int i = 0; i < 4; i++) {
            float rm = fmaxf(fmaxf(s[i][0], s[i][1]), fmaxf(s[i][2], s[i][3]));
            rm = fmaxf(rm, __shfl_xor_sync(0xffffffffu, rm, 8));
            rm = fmaxf(rm, __shfl_xor_sync(0xffffffffu, rm, 4));
            rm = fmaxf(rm, __shfl_xor_sync(0xffffffffu, rm, 2));
            rm = fmaxf(rm, __shfl_xor_sync(0xffffffffu, rm, 1));
            float mn = fmaxf(m[i], rm);
            float al = __expf(m[i] - mn);
            float ls = 0.f;
            #pragma unroll
            for (int j = 0; j < 4; j++) {
                s[i][j] = __expf(s[i][j] - mn);
                ls += s[i][j];
            }
            ls += __shfl_xor_sync(0xffffffffu, ls, 8);
            ls += __shfl_xor_sync(0xffffffffu, ls, 4);
            ls += __shfl_xor_sync(0xffffffffu, ls, 2);
            ls += __shfl_xor_sync(0xffffffffu, ls, 1);
            lsum[i] = lsum[i] * al + ls;
            m[i] = mn;
            #pragma unroll
            for (int j = 0; j < 4; j++) o[i][j] *= al;
            float4 pv = {s[i][0], s[i][1], s[i][2], s[i][3]};
            *(float4*)&Ps[((ty << 2) + i) * 64 + (tx << 2)] = pv;
        }
        __syncthreads();

        #pragma unroll 4
        for (int c = 0; c < 64; c++) {
            float4 b4 = *(const float4*)&Vs[c * 64 + (tx << 2)];
            #pragma unroll
            for (int i = 0; i < 4; i++) {
                float a = Ps[((ty << 2) + i) * 64 + c];
                o[i][0] += a * b4.x; o[i][1] += a * b4.y;
                o[i][2] += a * b4.z; o[i][3] += a * b4.w;
            }
        }
        __syncthreads();
    }

    const int b = bh >> 4, h = bh & 15;
    #pragma unroll
    for (int i = 0; i < 4; i++) {
        int row = q0 + (ty << 2) + i;
        float inv = 1.0f / (1.0f + lsum[i]);
        float4 ov = {o[i][0] * inv, o[i][1] * inv, o[i][2] * inv, o[i][3] * inv};
        *(float4*)&ctx[((size_t)(b * SEQ + row)) * DIM + h * HD + (tx << 2)] = ov;
    }
}

// ---------------------------------------------------------------------------
extern "C" void kernel_launch(void* const* d_in, const int* in_sizes, int n_in,
                              void* d_out, int out_size)
{
    const float* x  = (const float*)d_in[0];
    const float* Wq = (const float*)d_in[1];
    const float* bq = (const float*)d_in[2];
    const float* Wk = (const float*)d_in[3];
    const float* bk = (const float*)d_in[4];
    const float* Wv = (const float*)d_in[5];
    const float* bv = (const float*)d_in[6];
    const float* Wo = (const float*)d_in[7];
    const float* bo = (const float*)d_in[8];

    float *q, *k, *v, *ctx;
    cudaGetSymbolAddress((void**)&q,   g_q);
    cudaGetSymbolAddress((void**)&k,   g_k);
    cudaGetSymbolAddress((void**)&v,   g_v);
    cudaGetSymbolAddress((void**)&ctx, g_ctx);

    cudaFuncSetAttribute(attn_kernel,
                         cudaFuncAttributeMaxDynamicSharedMemorySize, 65536);

    dim3 gg(DIM / 128, MROWS / 128);   // (8, 32)
    gemm_tf32<<<gg, 256>>>(x, Wq, bq, q, 1);
    gemm_tf32<<<gg, 256>>>(x, Wk, bk, k, 1);
    gemm_tf32<<<gg, 256>>>(x, Wv, bv, v, 1);
    attn_kernel<<<dim3(SEQ / 64, BATCH * NH), 256, 65536>>>(q, k, v, ctx);
    gemm_tf32<<<gg, 256>>>(ctx, Wo, bo, (float*)d_out, 0);
}

// round 6
// speedup vs baseline: 2.4329x; 1.3572x over previous
#include <cuda_runtime.h>
#include <cstdint>

#define DIM 1024
#define NH 16
#define HD 64
#define BATCH 2
#define SEQ 2048
#define MROWS (BATCH*SEQ)   // 4096

// Scratch (allocation-free rule: __device__ globals)
__device__ float g_q[BATCH*NH*SEQ*HD];    // [b][h][l][hd]
__device__ float g_k[BATCH*NH*SEQ*HD];
__device__ float g_v[BATCH*NH*SEQ*HD];
__device__ float g_ctx[MROWS*DIM];        // [b*l][d]

__device__ __forceinline__ float to_tf32(float x) {
    float r;
    asm("cvt.rna.tf32.f32 %0, %1;" : "=f"(r) : "f"(x));
    return r;
}

__device__ __forceinline__ void mma_tf32(float d[4],
                                         uint32_t a0, uint32_t a1, uint32_t a2, uint32_t a3,
                                         uint32_t b0, uint32_t b1) {
    asm volatile(
        "mma.sync.aligned.m16n8k8.row.col.f32.tf32.tf32.f32 "
        "{%0,%1,%2,%3}, {%4,%5,%6,%7}, {%8,%9}, {%0,%1,%2,%3};"
        : "+f"(d[0]), "+f"(d[1]), "+f"(d[2]), "+f"(d[3])
        : "r"(a0), "r"(a1), "r"(a2), "r"(a3), "r"(b0), "r"(b1));
}

// ---------------------------------------------------------------------------
// tf32 tensor-core GEMM (unchanged from R5): out[M,N] = A[M,K] @ W[K,N] + bias
// ---------------------------------------------------------------------------
#define SST 136
__global__ __launch_bounds__(256) void gemm_tf32(
    const float* __restrict__ A, const float* __restrict__ W,
    const float* __restrict__ bias, float* __restrict__ out, int scatter)
{
    __shared__ float As[16 * SST];   // [k][m]
    __shared__ float Bs[16 * SST];   // [k][n]

    const int t    = threadIdx.x;
    const int warp = t >> 5, lane = t & 31;
    const int g  = lane >> 2;
    const int t4 = lane & 3;
    const int wm = (warp >> 2) << 6;
    const int wn = (warp & 3) << 5;
    const int m0 = blockIdx.y << 7, n0 = blockIdx.x << 7;

    float acc[4][4][4];
    #pragma unroll
    for (int mi = 0; mi < 4; mi++)
        #pragma unroll
        for (int ni = 0; ni < 4; ni++)
            #pragma unroll
            for (int e = 0; e < 4; e++) acc[mi][ni][e] = 0.f;

    for (int k0 = 0; k0 < DIM; k0 += 16) {
        #pragma unroll
        for (int i = 0; i < 2; i++) {
            int f = t + (i << 8);
            int r = f >> 2, kc = (f & 3) << 2;
            float4 v = *(const float4*)&A[(size_t)(m0 + r) * DIM + k0 + kc];
            As[(kc + 0) * SST + r] = to_tf32(v.x);
            As[(kc + 1) * SST + r] = to_tf32(v.y);
            As[(kc + 2) * SST + r] = to_tf32(v.z);
            As[(kc + 3) * SST + r] = to_tf32(v.w);
        }
        #pragma unroll
        for (int i = 0; i < 2; i++) {
            int f = t + (i << 8);
            int kr = f >> 5, nc = (f & 31) << 2;
            float4 v = *(const float4*)&W[(size_t)(k0 + kr) * DIM + n0 + nc];
            float4 c;
            c.x = to_tf32(v.x); c.y = to_tf32(v.y);
            c.z = to_tf32(v.z); c.w = to_tf32(v.w);
            *(float4*)&Bs[kr * SST + nc] = c;
        }
        __syncthreads();

        #pragma unroll
        for (int kk = 0; kk < 16; kk += 8) {
            uint32_t aF[4][4], bF[4][2];
            #pragma unroll
            for (int mi = 0; mi < 4; mi++) {
                int m = wm + (mi << 4);
                aF[mi][0] = __float_as_uint(As[(kk + t4) * SST + m + g]);
                aF[mi][1] = __float_as_uint(As[(kk + t4) * SST + m + g + 8]);
                aF[mi][2] = __float_as_uint(As[(kk + t4 + 4) * SST + m + g]);
                aF[mi][3] = __float_as_uint(As[(kk + t4 + 4) * SST + m + g + 8]);
            }
            #pragma unroll
            for (int ni = 0; ni < 4; ni++) {
                int n = wn + (ni << 3) + g;
                bF[ni][0] = __float_as_uint(Bs[(kk + t4) * SST + n]);
                bF[ni][1] = __float_as_uint(Bs[(kk + t4 + 4) * SST + n]);
            }
            #pragma unroll
            for (int mi = 0; mi < 4; mi++)
                #pragma unroll
                for (int ni = 0; ni < 4; ni++)
                    mma_tf32(acc[mi][ni], aF[mi][0], aF[mi][1], aF[mi][2], aF[mi][3],
                             bF[ni][0], bF[ni][1]);
        }
        __syncthreads();
    }

    #pragma unroll
    for (int mi = 0; mi < 4; mi++) {
        #pragma unroll
        for (int ni = 0; ni < 4; ni++) {
            int r0 = m0 + wm + (mi << 4) + g;
            int c0 = n0 + wn + (ni << 3) + (t4 << 1);
            float bx = bias[c0], by = bias[c0 + 1];
            #pragma unroll
            for (int half = 0; half < 2; half++) {
                int row = r0 + (half << 3);
                float2 o;
                o.x = acc[mi][ni][half * 2 + 0] + bx;
                o.y = acc[mi][ni][half * 2 + 1] + by;
                if (scatter) {
                    int b = row >> 11, l = row & 2047;
                    int h = c0 >> 6, dd = c0 & 63;
                    *(float2*)&out[((size_t)((b * NH + h) * SEQ) + l) * HD + dd] = o;
                } else {
                    *(float2*)&out[(size_t)row * DIM + c0] = o;
                }
            }
        }
    }
}

// ---------------------------------------------------------------------------
// Flash attention on tensor cores, 3xTF32 split precision (≈fp32 accuracy).
// BQ=128, BK=64. 8 warps, each warp owns an m16 q-slice over the full 64-key
// n-range. Q fragments pre-split into registers. K/V staged per key-tile as
// hi/lo smem (stride 68 -> conflict-free fragment LDS). Online quiet softmax
// (denom 1 + sum exp) in mma accumulator layout. P round-trips per-warp
// private smem rows (warp-local sync only).
// ---------------------------------------------------------------------------
#define PAD 68
__global__ __launch_bounds__(256, 1) void attn_mma(
    const float* __restrict__ gq, const float* __restrict__ gk,
    const float* __restrict__ gv, float* __restrict__ ctx)
{
    extern __shared__ float sm[];
    float* Kh = sm;                 // [64][PAD]
    float* Kl = Kh + 64 * PAD;
    float* Vh = Kl + 64 * PAD;
    float* Vl = Vh + 64 * PAD;
    float* Ph = Vl + 64 * PAD;      // [128][PAD]
    float* Pl = Ph + 128 * PAD;

    const int t    = threadIdx.x;
    const int warp = t >> 5, lane = t & 31;
    const int g  = lane >> 2;
    const int t4 = lane & 3;
    const int wq = warp << 4;             // q-row offset in block
    const int q0 = blockIdx.x << 7;
    const int bh = blockIdx.y;

    const float* Q = gq + (size_t)bh * SEQ * HD;
    const float* K = gk + (size_t)bh * SEQ * HD;
    const float* V = gv + (size_t)bh * SEQ * HD;

    // Pre-split Q fragments for all 8 k-steps
    uint32_t qh[8][4], ql[8][4];
    #pragma unroll
    for (int ks = 0; ks < 8; ks++) {
        #pragma unroll
        for (int e = 0; e < 4; e++) {
            int row = q0 + wq + g + ((e & 1) << 3);
            int col = (ks << 3) + t4 + ((e >> 1) << 2);
            float v = Q[(size_t)row * HD + col];
            float h = to_tf32(v);
            qh[ks][e] = __float_as_uint(h);
            ql[ks][e] = __float_as_uint(to_tf32(v - h));
        }
    }

    float oacc[8][4];
    #pragma unroll
    for (int ni = 0; ni < 8; ni++)
        #pragma unroll
        for (int e = 0; e < 4; e++) oacc[ni][e] = 0.f;
    float mrow[2] = {-1e30f, -1e30f};
    float lrow[2] = {0.f, 0.f};

    const int ktmax = (blockIdx.x << 1) + 1;
    for (int kt = 0; kt <= ktmax; kt++) {
        const int k0 = kt << 6;

        // Stage K/V tile, split hi/lo
        #pragma unroll
        for (int i = 0; i < 4; i++) {
            int f = t + (i << 8);
            int r = f >> 4, c4 = (f & 15) << 2;
            float4 kv = *(const float4*)&K[(size_t)(k0 + r) * HD + c4];
            float4 vv = *(const float4*)&V[(size_t)(k0 + r) * HD + c4];
            float4 h, l;
            h.x = to_tf32(kv.x); l.x = to_tf32(kv.x - h.x);
            h.y = to_tf32(kv.y); l.y = to_tf32(kv.y - h.y);
            h.z = to_tf32(kv.z); l.z = to_tf32(kv.z - h.z);
            h.w = to_tf32(kv.w); l.w = to_tf32(kv.w - h.w);
            *(float4*)&Kh[r * PAD + c4] = h;
            *(float4*)&Kl[r * PAD + c4] = l;
            h.x = to_tf32(vv.x); l.x = to_tf32(vv.x - h.x);
            h.y = to_tf32(vv.y); l.y = to_tf32(vv.y - h.y);
            h.z = to_tf32(vv.z); l.z = to_tf32(vv.z - h.z);
            h.w = to_tf32(vv.w); l.w = to_tf32(vv.w - h.w);
            *(float4*)&Vh[r * PAD + c4] = h;
            *(float4*)&Vl[r * PAD + c4] = l;
        }
        __syncthreads();

        // S = Q K^T (3xTF32)
        float sacc[8][4];
        #pragma unroll
        for (int ni = 0; ni < 8; ni++)
            #pragma unroll
            for (int e = 0; e < 4; e++) sacc[ni][e] = 0.f;

        #pragma unroll
        for (int ks = 0; ks < 8; ks++) {
            int kc = ks << 3;
            #pragma unroll
            for (int ni = 0; ni < 8; ni++) {
                int nrow = (ni << 3) + g;
                uint32_t kh0 = __float_as_uint(Kh[nrow * PAD + kc + t4]);
                uint32_t kh1 = __float_as_uint(Kh[nrow * PAD + kc + t4 + 4]);
                uint32_t kl0 = __float_as_uint(Kl[nrow * PAD + kc + t4]);
                uint32_t kl1 = __float_as_uint(Kl[nrow * PAD + kc + t4 + 4]);
                mma_tf32(sacc[ni], qh[ks][0], qh[ks][1], qh[ks][2], qh[ks][3], kh0, kh1);
                mma_tf32(sacc[ni], qh[ks][0], qh[ks][1], qh[ks][2], qh[ks][3], kl0, kl1);
                mma_tf32(sacc[ni], ql[ks][0], ql[ks][1], ql[ks][2], ql[ks][3], kh0, kh1);
            }
        }

        // Scale + causal mask (boundary tiles only)
        const bool need_mask = (kt >= ktmax - 1);
        #pragma unroll
        for (int ni = 0; ni < 8; ni++)
            #pragma unroll
            for (int e = 0; e < 4; e++) {
                float s = sacc[ni][e] * 0.125f;
                if (need_mask) {
                    int row = q0 + wq + g + ((e >> 1) << 3);
                    int col = k0 + (ni << 3) + (t4 << 1) + (e & 1);
                    if (col > row) s = -1e30f;
                }
                sacc[ni][e] = s;
            }

        // Online quiet softmax per row-half; write P (hi/lo) to warp-private smem
        #pragma unroll
        for (int hf = 0; hf < 2; hf++) {
            float rm = -1e30f;
            #pragma unroll
            for (int ni = 0; ni < 8; ni++)
                rm = fmaxf(rm, fmaxf(sacc[ni][2*hf], sacc[ni][2*hf+1]));
            rm = fmaxf(rm, __shfl_xor_sync(0xffffffffu, rm, 1));
            rm = fmaxf(rm, __shfl_xor_sync(0xffffffffu, rm, 2));
            float mn = fmaxf(mrow[hf], rm);
            float al = __expf(mrow[hf] - mn);
            float ls = 0.f;
            int prow = wq + g + (hf << 3);
            #pragma unroll
            for (int ni = 0; ni < 8; ni++) {
                float p0 = __expf(sacc[ni][2*hf]   - mn);
                float p1 = __expf(sacc[ni][2*hf+1] - mn);
                ls += p0 + p1;
                float h0 = to_tf32(p0), h1 = to_tf32(p1);
                float2 ph2 = {h0, h1};
                float2 pl2 = {to_tf32(p0 - h0), to_tf32(p1 - h1)};
                int pcol = (ni << 3) + (t4 << 1);
                *(float2*)&Ph[prow * PAD + pcol] = ph2;
                *(float2*)&Pl[prow * PAD + pcol] = pl2;
            }
            ls += __shfl_xor_sync(0xffffffffu, ls, 1);
            ls += __shfl_xor_sync(0xffffffffu, ls, 2);
            lrow[hf] = lrow[hf] * al + ls;
            mrow[hf] = mn;
            #pragma unroll
            for (int ni = 0; ni < 8; ni++) {
                oacc[ni][2*hf]   *= al;
                oacc[ni][2*hf+1] *= al;
            }
        }
        __syncwarp();   // P rows are warp-private; warp-level visibility suffices

        // O += P V (3xTF32)
        #pragma unroll
        for (int ks = 0; ks < 8; ks++) {
            int kc = ks << 3;
            uint32_t pah[4], pal[4];
            #pragma unroll
            for (int e = 0; e < 4; e++) {
                int prow = wq + g + ((e & 1) << 3);
                int pcol = kc + t4 + ((e >> 1) << 2);
                pah[e] = __float_as_uint(Ph[prow * PAD + pcol]);
                pal[e] = __float_as_uint(Pl[prow * PAD + pcol]);
            }
            #pragma unroll
            for (int ni = 0; ni < 8; ni++) {
                int nc = (ni << 3) + g;
                uint32_t vh0 = __float_as_uint(Vh[(kc + t4)     * PAD + nc]);
                uint32_t vh1 = __float_as_uint(Vh[(kc + t4 + 4) * PAD + nc]);
                uint32_t vl0 = __float_as_uint(Vl[(kc + t4)     * PAD + nc]);
                uint32_t vl1 = __float_as_uint(Vl[(kc + t4 + 4) * PAD + nc]);
                mma_tf32(oacc[ni], pah[0], pah[1], pah[2], pah[3], vh0, vh1);
                mma_tf32(oacc[ni], pah[0], pah[1], pah[2], pah[3], vl0, vl1);
                mma_tf32(oacc[ni], pal[0], pal[1], pal[2], pal[3], vh0, vh1);
            }
        }
        __syncthreads();   // before next tile overwrites Kh/Kl/Vh/Vl
    }

    // Epilogue: divide by (1 + l), write ctx in [b*l][d] layout
    const int b = bh >> 4, hh = bh & 15;
    #pragma unroll
    for (int hf = 0; hf < 2; hf++) {
        float inv = 1.0f / (1.0f + lrow[hf]);
        int row = q0 + wq + g + (hf << 3);
        #pragma unroll
        for (int ni = 0; ni < 8; ni++) {
            float2 o = { oacc[ni][2*hf] * inv, oacc[ni][2*hf+1] * inv };
            int d = (ni << 3) + (t4 << 1);
            *(float2*)&ctx[((size_t)(b * SEQ + row)) * DIM + hh * HD + d] = o;
        }
    }
}

// ---------------------------------------------------------------------------
extern "C" void kernel_launch(void* const* d_in, const int* in_sizes, int n_in,
                              void* d_out, int out_size)
{
    const float* x  = (const float*)d_in[0];
    const float* Wq = (const float*)d_in[1];
    const float* bq = (const float*)d_in[2];
    const float* Wk = (const float*)d_in[3];
    const float* bk = (const float*)d_in[4];
    const float* Wv = (const float*)d_in[5];
    const float* bv = (const float*)d_in[6];
    const float* Wo = (const float*)d_in[7];
    const float* bo = (const float*)d_in[8];

    float *q, *k, *v, *ctx;
    cudaGetSymbolAddress((void**)&q,   g_q);
    cudaGetSymbolAddress((void**)&k,   g_k);
    cudaGetSymbolAddress((void**)&v,   g_v);
    cudaGetSymbolAddress((void**)&ctx, g_ctx);

    const int attn_smem = (4 * 64 * PAD + 2 * 128 * PAD) * sizeof(float);  // 139264
    cudaFuncSetAttribute(attn_mma,
                         cudaFuncAttributeMaxDynamicSharedMemorySize, attn_smem);

    dim3 gg(DIM / 128, MROWS / 128);   // (8, 32)
    gemm_tf32<<<gg, 256>>>(x, Wq, bq, q, 1);
    gemm_tf32<<<gg, 256>>>(x, Wk, bk, k, 1);
    gemm_tf32<<<gg, 256>>>(x, Wv, bv, v, 1);
    attn_mma<<<dim3(SEQ / 128, BATCH * NH), 256, attn_smem>>>(q, k, v, ctx);
    gemm_tf32<<<gg, 256>>>(ctx, Wo, bo, (float*)d_out, 0);
}

// round 11
// speedup vs baseline: 2.4900x; 1.0235x over previous
#include <cuda_runtime.h>
#include <cstdint>

#define DIM 1024
#define NH 16
#define HD 64
#define BATCH 2
#define SEQ 2048
#define MROWS (BATCH*SEQ)   // 4096

// Scratch (allocation-free rule: __device__ globals)
__device__ float g_q[BATCH*NH*SEQ*HD];    // [b][h][l][hd]
__device__ float g_k[BATCH*NH*SEQ*HD];
__device__ float g_v[BATCH*NH*SEQ*HD];
__device__ float g_ctx[MROWS*DIM];        // [b*l][d]

__device__ __forceinline__ float to_tf32(float x) {
    float r;
    asm("cvt.rna.tf32.f32 %0, %1;" : "=f"(r) : "f"(x));
    return r;
}

__device__ __forceinline__ void mma_tf32(float d[4],
                                         uint32_t a0, uint32_t a1, uint32_t a2, uint32_t a3,
                                         uint32_t b0, uint32_t b1) {
    asm volatile(
        "mma.sync.aligned.m16n8k8.row.col.f32.tf32.tf32.f32 "
        "{%0,%1,%2,%3}, {%4,%5,%6,%7}, {%8,%9}, {%0,%1,%2,%3};"
        : "+f"(d[0]), "+f"(d[1]), "+f"(d[2]), "+f"(d[3])
        : "r"(a0), "r"(a1), "r"(a2), "r"(a3), "r"(b0), "r"(b1));
}

// ---------------------------------------------------------------------------
// tf32 tensor-core GEMM (unchanged): out[M,N] = A[M,K] @ W[K,N] + bias
// ---------------------------------------------------------------------------
#define SST 136
__global__ __launch_bounds__(256) void gemm_tf32(
    const float* __restrict__ A, const float* __restrict__ W,
    const float* __restrict__ bias, float* __restrict__ out, int scatter)
{
    __shared__ float As[16 * SST];   // [k][m]
    __shared__ float Bs[16 * SST];   // [k][n]

    const int t    = threadIdx.x;
    const int warp = t >> 5, lane = t & 31;
    const int g  = lane >> 2;
    const int t4 = lane & 3;
    const int wm = (warp >> 2) << 6;
    const int wn = (warp & 3) << 5;
    const int m0 = blockIdx.y << 7, n0 = blockIdx.x << 7;

    float acc[4][4][4];
    #pragma unroll
    for (int mi = 0; mi < 4; mi++)
        #pragma unroll
        for (int ni = 0; ni < 4; ni++)
            #pragma unroll
            for (int e = 0; e < 4; e++) acc[mi][ni][e] = 0.f;

    for (int k0 = 0; k0 < DIM; k0 += 16) {
        #pragma unroll
        for (int i = 0; i < 2; i++) {
            int f = t + (i << 8);
            int r = f >> 2, kc = (f & 3) << 2;
            float4 v = *(const float4*)&A[(size_t)(m0 + r) * DIM + k0 + kc];
            As[(kc + 0) * SST + r] = to_tf32(v.x);
            As[(kc + 1) * SST + r] = to_tf32(v.y);
            As[(kc + 2) * SST + r] = to_tf32(v.z);
            As[(kc + 3) * SST + r] = to_tf32(v.w);
        }
        #pragma unroll
        for (int i = 0; i < 2; i++) {
            int f = t + (i << 8);
            int kr = f >> 5, nc = (f & 31) << 2;
            float4 v = *(const float4*)&W[(size_t)(k0 + kr) * DIM + n0 + nc];
            float4 c;
            c.x = to_tf32(v.x); c.y = to_tf32(v.y);
            c.z = to_tf32(v.z); c.w = to_tf32(v.w);
            *(float4*)&Bs[kr * SST + nc] = c;
        }
        __syncthreads();

        #pragma unroll
        for (int kk = 0; kk < 16; kk += 8) {
            uint32_t aF[4][4], bF[4][2];
            #pragma unroll
            for (int mi = 0; mi < 4; mi++) {
                int m = wm + (mi << 4);
                aF[mi][0] = __float_as_uint(As[(kk + t4) * SST + m + g]);
                aF[mi][1] = __float_as_uint(As[(kk + t4) * SST + m + g + 8]);
                aF[mi][2] = __float_as_uint(As[(kk + t4 + 4) * SST + m + g]);
                aF[mi][3] = __float_as_uint(As[(kk + t4 + 4) * SST + m + g + 8]);
            }
            #pragma unroll
            for (int ni = 0; ni < 4; ni++) {
                int n = wn + (ni << 3) + g;
                bF[ni][0] = __float_as_uint(Bs[(kk + t4) * SST + n]);
                bF[ni][1] = __float_as_uint(Bs[(kk + t4 + 4) * SST + n]);
            }
            #pragma unroll
            for (int mi = 0; mi < 4; mi++)
                #pragma unroll
                for (int ni = 0; ni < 4; ni++)
                    mma_tf32(acc[mi][ni], aF[mi][0], aF[mi][1], aF[mi][2], aF[mi][3],
                             bF[ni][0], bF[ni][1]);
        }
        __syncthreads();
    }

    #pragma unroll
    for (int mi = 0; mi < 4; mi++) {
        #pragma unroll
        for (int ni = 0; ni < 4; ni++) {
            int r0 = m0 + wm + (mi << 4) + g;
            int c0 = n0 + wn + (ni << 3) + (t4 << 1);
            float bx = bias[c0], by = bias[c0 + 1];
            #pragma unroll
            for (int half = 0; half < 2; half++) {
                int row = r0 + (half << 3);
                float2 o;
                o.x = acc[mi][ni][half * 2 + 0] + bx;
                o.y = acc[mi][ni][half * 2 + 1] + by;
                if (scatter) {
                    int b = row >> 11, l = row & 2047;
                    int h = c0 >> 6, dd = c0 & 63;
                    *(float2*)&out[((size_t)((b * NH + h) * SEQ) + l) * HD + dd] = o;
                } else {
                    *(float2*)&out[(size_t)row * DIM + c0] = o;
                }
            }
        }
    }
}

// ---------------------------------------------------------------------------
// Flash attention on tensor cores, 3xTF32 (≈fp32 accuracy).
// R7: K/V smem stores (hi,lo) interleaved as float2 -> fragment fetch is one
// LDS.64; P transposed C->A layout via exact quad shuffles (no smem P);
// reversed q-block index for causal load balance. BQ=128, BK=64, 8 warps.
// ---------------------------------------------------------------------------
#define PAD2 68   // float2 row stride (=136 words, ≡8 mod 32 -> conflict-free)
__global__ __launch_bounds__(256, 1) void attn_mma(
    const float* __restrict__ gq, const float* __restrict__ gk,
    const float* __restrict__ gv, float* __restrict__ ctx)
{
    extern __shared__ float2 sm2[];
    float2* Khl = sm2;               // [64][PAD2]  (.x=hi, .y=lo)
    float2* Vhl = sm2 + 64 * PAD2;   // [64][PAD2]

    const int t    = threadIdx.x;
    const int warp = t >> 5, lane = t & 31;
    const int g  = lane >> 2;
    const int t4 = lane & 3;
    const int wq = warp << 4;
    const int qb = (int)gridDim.x - 1 - (int)blockIdx.x;  // heavy tiles first
    const int q0 = qb << 7;
    const int bh = blockIdx.y;

    const float* Q = gq + (size_t)bh * SEQ * HD;
    const float* K = gk + (size_t)bh * SEQ * HD;
    const float* V = gv + (size_t)bh * SEQ * HD;

    // Pre-split Q fragments for all 8 k-steps
    uint32_t qh[8][4], ql[8][4];
    #pragma unroll
    for (int ks = 0; ks < 8; ks++) {
        #pragma unroll
        for (int e = 0; e < 4; e++) {
            int row = q0 + wq + g + ((e & 1) << 3);
            int col = (ks << 3) + t4 + ((e >> 1) << 2);
            float v = Q[(size_t)row * HD + col];
            float h = to_tf32(v);
            qh[ks][e] = __float_as_uint(h);
            ql[ks][e] = __float_as_uint(to_tf32(v - h));
        }
    }

    float oacc[8][4];
    #pragma unroll
    for (int ni = 0; ni < 8; ni++)
        #pragma unroll
        for (int e = 0; e < 4; e++) oacc[ni][e] = 0.f;
    float mrow[2] = {-1e30f, -1e30f};
    float lrow[2] = {0.f, 0.f};

    const int o1lane = (lane & 28) | (t4 >> 1);   // owner of col t4
    const int o2lane = o1lane + 2;                // owner of col t4+4
    const bool odd = (t4 & 1);

    const int ktmax = (qb << 1) + 1;
    for (int kt = 0; kt <= ktmax; kt++) {
        const int k0 = kt << 6;

        // Stage K/V tile: (hi,lo) interleaved float2; conflict-free STS.128
        #pragma unroll
        for (int i = 0; i < 8; i++) {
            int f = t + (i << 8);            // 0..2047
            int r = f >> 5;                  // key row 0..63
            int c = (f & 31) << 1;           // feature col (even)
            float2 kv = *(const float2*)&K[(size_t)(k0 + r) * HD + c];
            float hx = to_tf32(kv.x), hy = to_tf32(kv.y);
            float4 stk = {hx, to_tf32(kv.x - hx), hy, to_tf32(kv.y - hy)};
            *(float4*)&Khl[r * PAD2 + c] = stk;
            float2 vv = *(const float2*)&V[(size_t)(k0 + r) * HD + c];
            hx = to_tf32(vv.x); hy = to_tf32(vv.y);
            float4 stv = {hx, to_tf32(vv.x - hx), hy, to_tf32(vv.y - hy)};
            *(float4*)&Vhl[r * PAD2 + c] = stv;
        }
        __syncthreads();

        // S = Q K^T (3xTF32); B fragment = one LDS.64 per (ks,ni,half)
        float sacc[8][4];
        #pragma unroll
        for (int ni = 0; ni < 8; ni++)
            #pragma unroll
            for (int e = 0; e < 4; e++) sacc[ni][e] = 0.f;

        #pragma unroll
        for (int ks = 0; ks < 8; ks++) {
            int kc = ks << 3;
            #pragma unroll
            for (int ni = 0; ni < 8; ni++) {
                int nrow = (ni << 3) + g;
                float2 kv0 = Khl[nrow * PAD2 + kc + t4];
                float2 kv1 = Khl[nrow * PAD2 + kc + t4 + 4];
                uint32_t kh0 = __float_as_uint(kv0.x), kh1 = __float_as_uint(kv1.x);
                uint32_t kl0 = __float_as_uint(kv0.y), kl1 = __float_as_uint(kv1.y);
                mma_tf32(sacc[ni], qh[ks][0], qh[ks][1], qh[ks][2], qh[ks][3], kh0, kh1);
                mma_tf32(sacc[ni], qh[ks][0], qh[ks][1], qh[ks][2], qh[ks][3], kl0, kl1);
                mma_tf32(sacc[ni], ql[ks][0], ql[ks][1], ql[ks][2], ql[ks][3], kh0, kh1);
            }
        }

        // Scale + causal mask (two boundary tiles only)
        const bool need_mask = (kt >= ktmax - 1);
        #pragma unroll
        for (int ni = 0; ni < 8; ni++)
            #pragma unroll
            for (int e = 0; e < 4; e++) {
                float s = sacc[ni][e] * 0.125f;
                if (need_mask) {
                    int row = q0 + wq + g + ((e >> 1) << 3);
                    int col = k0 + (ni << 3) + (t4 << 1) + (e & 1);
                    if (col > row) s = -1e30f;
                }
                sacc[ni][e] = s;
            }

        // Online quiet softmax; p values stay in sacc
        #pragma unroll
        for (int hf = 0; hf < 2; hf++) {
            float rm = -1e30f;
            #pragma unroll
            for (int ni = 0; ni < 8; ni++)
                rm = fmaxf(rm, fmaxf(sacc[ni][2*hf], sacc[ni][2*hf+1]));
            rm = fmaxf(rm, __shfl_xor_sync(0xffffffffu, rm, 1));
            rm = fmaxf(rm, __shfl_xor_sync(0xffffffffu, rm, 2));
            float mn = fmaxf(mrow[hf], rm);
            float al = __expf(mrow[hf] - mn);
            float ls = 0.f;
            #pragma unroll
            for (int ni = 0; ni < 8; ni++) {
                float p0 = __expf(sacc[ni][2*hf]   - mn);
                float p1 = __expf(sacc[ni][2*hf+1] - mn);
                sacc[ni][2*hf]   = p0;
                sacc[ni][2*hf+1] = p1;
                ls += p0 + p1;
            }
            ls += __shfl_xor_sync(0xffffffffu, ls, 1);
            ls += __shfl_xor_sync(0xffffffffu, ls, 2);
            lrow[hf] = lrow[hf] * al + ls;
            mrow[hf] = mn;
            #pragma unroll
            for (int ni = 0; ni < 8; ni++) {
                oacc[ni][2*hf]   *= al;
                oacc[ni][2*hf+1] *= al;
            }
        }

        // O += P V (3xTF32). P C-layout -> A-layout via exact quad shuffles.
        #pragma unroll
        for (int ks = 0; ks < 8; ks++) {
            int kc = ks << 3;
            float pe0 = sacc[ks][0], po0 = sacc[ks][1];   // row g   cols 2t4,2t4+1
            float pe1 = sacc[ks][2], po1 = sacc[ks][3];   // row g+8
            float e, o_;
            e  = __shfl_sync(0xffffffffu, pe0, o1lane);
            o_ = __shfl_sync(0xffffffffu, po0, o1lane);
            float a0 = odd ? o_ : e;                      // (g, t4)
            e  = __shfl_sync(0xffffffffu, pe1, o1lane);
            o_ = __shfl_sync(0xffffffffu, po1, o1lane);
            float a1 = odd ? o_ : e;                      // (g+8, t4)
            e  = __shfl_sync(0xffffffffu, pe0, o2lane);
            o_ = __shfl_sync(0xffffffffu, po0, o2lane);
            float a2 = odd ? o_ : e;                      // (g, t4+4)
            e  = __shfl_sync(0xffffffffu, pe1, o2lane);
            o_ = __shfl_sync(0xffffffffu, po1, o2lane);
            float a3 = odd ? o_ : e;                      // (g+8, t4+4)

            float h0 = to_tf32(a0), h1 = to_tf32(a1);
            float h2 = to_tf32(a2), h3 = to_tf32(a3);
            uint32_t pah[4] = {__float_as_uint(h0), __float_as_uint(h1),
                               __float_as_uint(h2), __float_as_uint(h3)};
            uint32_t pal[4] = {__float_as_uint(to_tf32(a0 - h0)),
                               __float_as_uint(to_tf32(a1 - h1)),
                               __float_as_uint(to_tf32(a2 - h2)),
                               __float_as_uint(to_tf32(a3 - h3))};
            #pragma unroll
            for (int ni = 0; ni < 8; ni++) {
                int nc = (ni << 3) + g;
                float2 v0 = Vhl[(kc + t4)     * PAD2 + nc];
                float2 v1 = Vhl[(kc + t4 + 4) * PAD2 + nc];
                uint32_t vh0 = __float_as_uint(v0.x), vh1 = __float_as_uint(v1.x);
                uint32_t vl0 = __float_as_uint(v0.y), vl1 = __float_as_uint(v1.y);
                mma_tf32(oacc[ni], pah[0], pah[1], pah[2], pah[3], vh0, vh1);
                mma_tf32(oacc[ni], pah[0], pah[1], pah[2], pah[3], vl0, vl1);
                mma_tf32(oacc[ni], pal[0], pal[1], pal[2], pal[3], vh0, vh1);
            }
        }
        __syncthreads();   // before next tile overwrites Khl/Vhl
    }

    // Epilogue: divide by (1 + l), write ctx in [b*l][d] layout
    const int b = bh >> 4, hh = bh & 15;
    #pragma unroll
    for (int hf = 0; hf < 2; hf++) {
        float inv = 1.0f / (1.0f + lrow[hf]);
        int row = q0 + wq + g + (hf << 3);
        #pragma unroll
        for (int ni = 0; ni < 8; ni++) {
            float2 o = { oacc[ni][2*hf] * inv, oacc[ni][2*hf+1] * inv };
            int d = (ni << 3) + (t4 << 1);
            *(float2*)&ctx[((size_t)(b * SEQ + row)) * DIM + hh * HD + d] = o;
        }
    }
}

// ---------------------------------------------------------------------------
extern "C" void kernel_launch(void* const* d_in, const int* in_sizes, int n_in,
                              void* d_out, int out_size)
{
    const float* x  = (const float*)d_in[0];
    const float* Wq = (const float*)d_in[1];
    const float* bq = (const float*)d_in[2];
    const float* Wk = (const float*)d_in[3];
    const float* bk = (const float*)d_in[4];
    const float* Wv = (const float*)d_in[5];
    const float* bv = (const float*)d_in[6];
    const float* Wo = (const float*)d_in[7];
    const float* bo = (const float*)d_in[8];

    float *q, *k, *v, *ctx;
    cudaGetSymbolAddress((void**)&q,   g_q);
    cudaGetSymbolAddress((void**)&k,   g_k);
    cudaGetSymbolAddress((void**)&v,   g_v);
    cudaGetSymbolAddress((void**)&ctx, g_ctx);

    const int attn_smem = 2 * 64 * PAD2 * sizeof(float2);  // 69632
    cudaFuncSetAttribute(attn_mma,
                         cudaFuncAttributeMaxDynamicSharedMemorySize, attn_smem);

    dim3 gg(DIM / 128, MROWS / 128);   // (8, 32)
    gemm_tf32<<<gg, 256>>>(x, Wq, bq, q, 1);
    gemm_tf32<<<gg, 256>>>(x, Wk, bk, k, 1);
    gemm_tf32<<<gg, 256>>>(x, Wv, bv, v, 1);
    attn_mma<<<dim3(SEQ / 128, BATCH * NH), 256, attn_smem>>>(q, k, v, ctx);
    gemm_tf32<<<gg, 256>>>(ctx, Wo, bo, (float*)d_out, 0);
}

// round 12
// speedup vs baseline: 2.5835x; 1.0376x over previous
#include <cuda_runtime.h>
#include <cstdint>

#define DIM 1024
#define NH 16
#define HD 64
#define BATCH 2
#define SEQ 2048
#define MROWS (BATCH*SEQ)   // 4096

// Scratch (allocation-free rule: __device__ globals)
__device__ float g_q[BATCH*NH*SEQ*HD];    // [b][h][l][hd]
__device__ float g_k[BATCH*NH*SEQ*HD];
__device__ float g_v[BATCH*NH*SEQ*HD];
__device__ float g_ctx[MROWS*DIM];        // [b*l][d]

__device__ __forceinline__ float to_tf32(float x) {
    float r;
    asm("cvt.rna.tf32.f32 %0, %1;" : "=f"(r) : "f"(x));
    return r;
}

__device__ __forceinline__ void mma_tf32(float d[4],
                                         uint32_t a0, uint32_t a1, uint32_t a2, uint32_t a3,
                                         uint32_t b0, uint32_t b1) {
    asm volatile(
        "mma.sync.aligned.m16n8k8.row.col.f32.tf32.tf32.f32 "
        "{%0,%1,%2,%3}, {%4,%5,%6,%7}, {%8,%9}, {%0,%1,%2,%3};"
        : "+f"(d[0]), "+f"(d[1]), "+f"(d[2]), "+f"(d[3])
        : "r"(a0), "r"(a1), "r"(a2), "r"(a3), "r"(b0), "r"(b1));
}

// ---------------------------------------------------------------------------
// tf32 tensor-core GEMM, double-buffered staging (R12).
// out[M,N] = A[M,K] @ W[K,N] + bias.  BM=BN=128, BK=16, 256 thr, 8 warps.
// ---------------------------------------------------------------------------
#define SST 136
__device__ __forceinline__ void gemm_stage(
    const float* __restrict__ A, const float* __restrict__ W,
    float* As, float* Bs, int m0, int n0, int k0, int t)
{
    #pragma unroll
    for (int i = 0; i < 2; i++) {
        int f = t + (i << 8);
        int r = f >> 2, kc = (f & 3) << 2;
        float4 v = *(const float4*)&A[(size_t)(m0 + r) * DIM + k0 + kc];
        As[(kc + 0) * SST + r] = to_tf32(v.x);
        As[(kc + 1) * SST + r] = to_tf32(v.y);
        As[(kc + 2) * SST + r] = to_tf32(v.z);
        As[(kc + 3) * SST + r] = to_tf32(v.w);
    }
    #pragma unroll
    for (int i = 0; i < 2; i++) {
        int f = t + (i << 8);
        int kr = f >> 5, nc = (f & 31) << 2;
        float4 v = *(const float4*)&W[(size_t)(k0 + kr) * DIM + n0 + nc];
        float4 c;
        c.x = to_tf32(v.x); c.y = to_tf32(v.y);
        c.z = to_tf32(v.z); c.w = to_tf32(v.w);
        *(float4*)&Bs[kr * SST + nc] = c;
    }
}

__global__ __launch_bounds__(256) void gemm_tf32(
    const float* __restrict__ A, const float* __restrict__ W,
    const float* __restrict__ bias, float* __restrict__ out, int scatter)
{
    __shared__ float As[2][16 * SST];
    __shared__ float Bs[2][16 * SST];

    const int t    = threadIdx.x;
    const int warp = t >> 5, lane = t & 31;
    const int g  = lane >> 2;
    const int t4 = lane & 3;
    const int wm = (warp >> 2) << 6;
    const int wn = (warp & 3) << 5;
    const int m0 = blockIdx.y << 7, n0 = blockIdx.x << 7;

    float acc[4][4][4];
    #pragma unroll
    for (int mi = 0; mi < 4; mi++)
        #pragma unroll
        for (int ni = 0; ni < 4; ni++)
            #pragma unroll
            for (int e = 0; e < 4; e++) acc[mi][ni][e] = 0.f;

    gemm_stage(A, W, As[0], Bs[0], m0, n0, 0, t);

    int buf = 0;
    for (int k0 = 0; k0 < DIM; k0 += 16) {
        __syncthreads();
        if (k0 + 16 < DIM)
            gemm_stage(A, W, As[buf ^ 1], Bs[buf ^ 1], m0, n0, k0 + 16, t);

        const float* Ab = As[buf];
        const float* Bb = Bs[buf];
        #pragma unroll
        for (int kk = 0; kk < 16; kk += 8) {
            uint32_t aF[4][4], bF[4][2];
            #pragma unroll
            for (int mi = 0; mi < 4; mi++) {
                int m = wm + (mi << 4);
                aF[mi][0] = __float_as_uint(Ab[(kk + t4) * SST + m + g]);
                aF[mi][1] = __float_as_uint(Ab[(kk + t4) * SST + m + g + 8]);
                aF[mi][2] = __float_as_uint(Ab[(kk + t4 + 4) * SST + m + g]);
                aF[mi][3] = __float_as_uint(Ab[(kk + t4 + 4) * SST + m + g + 8]);
            }
            #pragma unroll
            for (int ni = 0; ni < 4; ni++) {
                int n = wn + (ni << 3) + g;
                bF[ni][0] = __float_as_uint(Bb[(kk + t4) * SST + n]);
                bF[ni][1] = __float_as_uint(Bb[(kk + t4 + 4) * SST + n]);
            }
            #pragma unroll
            for (int mi = 0; mi < 4; mi++)
                #pragma unroll
                for (int ni = 0; ni < 4; ni++)
                    mma_tf32(acc[mi][ni], aF[mi][0], aF[mi][1], aF[mi][2], aF[mi][3],
                             bF[ni][0], bF[ni][1]);
        }
        buf ^= 1;
    }

    #pragma unroll
    for (int mi = 0; mi < 4; mi++) {
        #pragma unroll
        for (int ni = 0; ni < 4; ni++) {
            int r0 = m0 + wm + (mi << 4) + g;
            int c0 = n0 + wn + (ni << 3) + (t4 << 1);
            float bx = bias[c0], by = bias[c0 + 1];
            #pragma unroll
            for (int half = 0; half < 2; half++) {
                int row = r0 + (half << 3);
                float2 o;
                o.x = acc[mi][ni][half * 2 + 0] + bx;
                o.y = acc[mi][ni][half * 2 + 1] + by;
                if (scatter) {
                    int b = row >> 11, l = row & 2047;
                    int h = c0 >> 6, dd = c0 & 63;
                    *(float2*)&out[((size_t)((b * NH + h) * SEQ) + l) * HD + dd] = o;
                } else {
                    *(float2*)&out[(size_t)row * DIM + c0] = o;
                }
            }
        }
    }
}

// ---------------------------------------------------------------------------
// Flash attention on tensor cores.
// S = QK^T in 3xTF32 (exact-enough); PV = P_hi * (V_hi + V_lo) (2 terms).
// R12: double-buffered K/V staging (1 sync/tile, LDG hidden behind
// softmax+PV), exp2-domain softmax, quad-shuffle P transpose (no P smem).
// BQ=128, BK=64, 8 warps. Quiet softmax: denom = 1 + sum exp.
// ---------------------------------------------------------------------------
#define PAD2 68   // float2 row stride (=136 words, ≡8 mod 32 -> conflict-free)
#define SCALE2 0.1803368801111204f   // 0.125 * log2(e)

__device__ __forceinline__ void attn_stage(
    const float* __restrict__ K, const float* __restrict__ V,
    float2* Kb, float2* Vb, int k0, int t)
{
    #pragma unroll
    for (int i = 0; i < 8; i++) {
        int f = t + (i << 8);            // 0..2047
        int r = f >> 5;                  // key row 0..63
        int c = (f & 31) << 1;           // feature col (even)
        float2 kv = *(const float2*)&K[(size_t)(k0 + r) * HD + c];
        float hx = to_tf32(kv.x), hy = to_tf32(kv.y);
        float4 stk = {hx, to_tf32(kv.x - hx), hy, to_tf32(kv.y - hy)};
        *(float4*)&Kb[r * PAD2 + c] = stk;
        float2 vv = *(const float2*)&V[(size_t)(k0 + r) * HD + c];
        hx = to_tf32(vv.x); hy = to_tf32(vv.y);
        float4 stv = {hx, to_tf32(vv.x - hx), hy, to_tf32(vv.y - hy)};
        *(float4*)&Vb[r * PAD2 + c] = stv;
    }
}

__global__ __launch_bounds__(256, 1) void attn_mma(
    const float* __restrict__ gq, const float* __restrict__ gk,
    const float* __restrict__ gv, float* __restrict__ ctx)
{
    extern __shared__ float2 sm2[];
    float2* Kbuf[2] = { sm2,             sm2 + 64 * PAD2 };
    float2* Vbuf[2] = { sm2 + 2*64*PAD2, sm2 + 3*64*PAD2 };

    const int t    = threadIdx.x;
    const int warp = t >> 5, lane = t & 31;
    const int g  = lane >> 2;
    const int t4 = lane & 3;
    const int wq = warp << 4;
    const int qb = (int)gridDim.x - 1 - (int)blockIdx.x;  // heavy tiles first
    const int q0 = qb << 7;
    const int bh = blockIdx.y;

    const float* Q = gq + (size_t)bh * SEQ * HD;
    const float* K = gk + (size_t)bh * SEQ * HD;
    const float* V = gv + (size_t)bh * SEQ * HD;

    // Pre-split Q fragments for all 8 k-steps
    uint32_t qh[8][4], ql[8][4];
    #pragma unroll
    for (int ks = 0; ks < 8; ks++) {
        #pragma unroll
        for (int e = 0; e < 4; e++) {
            int row = q0 + wq + g + ((e & 1) << 3);
            int col = (ks << 3) + t4 + ((e >> 1) << 2);
            float v = Q[(size_t)row * HD + col];
            float h = to_tf32(v);
            qh[ks][e] = __float_as_uint(h);
            ql[ks][e] = __float_as_uint(to_tf32(v - h));
        }
    }

    float oacc[8][4];
    #pragma unroll
    for (int ni = 0; ni < 8; ni++)
        #pragma unroll
        for (int e = 0; e < 4; e++) oacc[ni][e] = 0.f;
    float mrow[2] = {-1e30f, -1e30f};   // base-2 domain
    float lrow[2] = {0.f, 0.f};

    const int o1lane = (lane & 28) | (t4 >> 1);   // owner of col t4
    const int o2lane = o1lane + 2;                // owner of col t4+4
    const bool odd = (t4 & 1);

    const int ktmax = (qb << 1) + 1;

    attn_stage(K, V, Kbuf[0], Vbuf[0], 0, t);

    for (int kt = 0; kt <= ktmax; kt++) {
        const int k0 = kt << 6;
        const float2* Kb = Kbuf[kt & 1];
        const float2* Vb = Vbuf[kt & 1];
        __syncthreads();   // staging of tile kt complete; prev compute done

        // ---- S = Q K^T (3xTF32) ----
        float sacc[8][4];
        #pragma unroll
        for (int ni = 0; ni < 8; ni++)
            #pragma unroll
            for (int e = 0; e < 4; e++) sacc[ni][e] = 0.f;

        #pragma unroll
        for (int ks = 0; ks < 8; ks++) {
            int kc = ks << 3;
            #pragma unroll
            for (int ni = 0; ni < 8; ni++) {
                int nrow = (ni << 3) + g;
                float2 kv0 = Kb[nrow * PAD2 + kc + t4];
                float2 kv1 = Kb[nrow * PAD2 + kc + t4 + 4];
                uint32_t kh0 = __float_as_uint(kv0.x), kh1 = __float_as_uint(kv1.x);
                uint32_t kl0 = __float_as_uint(kv0.y), kl1 = __float_as_uint(kv1.y);
                mma_tf32(sacc[ni], qh[ks][0], qh[ks][1], qh[ks][2], qh[ks][3], kh0, kh1);
                mma_tf32(sacc[ni], qh[ks][0], qh[ks][1], qh[ks][2], qh[ks][3], kl0, kl1);
                mma_tf32(sacc[ni], ql[ks][0], ql[ks][1], ql[ks][2], ql[ks][3], kh0, kh1);
            }
        }

        // ---- prefetch next tile (LDG latency hides behind softmax+PV) ----
        if (kt < ktmax)
            attn_stage(K, V, Kbuf[(kt + 1) & 1], Vbuf[(kt + 1) & 1],
                       (kt + 1) << 6, t);

        // ---- scale to base-2 domain + causal mask (boundary tiles) ----
        const bool need_mask = (kt >= ktmax - 1);
        #pragma unroll
        for (int ni = 0; ni < 8; ni++)
            #pragma unroll
            for (int e = 0; e < 4; e++) {
                float s = sacc[ni][e] * SCALE2;
                if (need_mask) {
                    int row = q0 + wq + g + ((e >> 1) << 3);
                    int col = k0 + (ni << 3) + (t4 << 1) + (e & 1);
                    if (col > row) s = -1e30f;
                }
                sacc[ni][e] = s;
            }

        // ---- online quiet softmax (exp2 domain) ----
        #pragma unroll
        for (int hf = 0; hf < 2; hf++) {
            float rm = -1e30f;
            #pragma unroll
            for (int ni = 0; ni < 8; ni++)
                rm = fmaxf(rm, fmaxf(sacc[ni][2*hf], sacc[ni][2*hf+1]));
            rm = fmaxf(rm, __shfl_xor_sync(0xffffffffu, rm, 1));
            rm = fmaxf(rm, __shfl_xor_sync(0xffffffffu, rm, 2));
            float mn = fmaxf(mrow[hf], rm);
            float al = exp2f(mrow[hf] - mn);
            float ls = 0.f;
            #pragma unroll
            for (int ni = 0; ni < 8; ni++) {
                float p0 = exp2f(sacc[ni][2*hf]   - mn);
                float p1 = exp2f(sacc[ni][2*hf+1] - mn);
                sacc[ni][2*hf]   = p0;
                sacc[ni][2*hf+1] = p1;
                ls += p0 + p1;
            }
            ls += __shfl_xor_sync(0xffffffffu, ls, 1);
            ls += __shfl_xor_sync(0xffffffffu, ls, 2);
            lrow[hf] = lrow[hf] * al + ls;
            mrow[hf] = mn;
            #pragma unroll
            for (int ni = 0; ni < 8; ni++) {
                oacc[ni][2*hf]   *= al;
                oacc[ni][2*hf+1] *= al;
            }
        }

        // ---- O += P_hi * V (2-term). P C->A layout via exact quad shuffles.
        #pragma unroll
        for (int ks = 0; ks < 8; ks++) {
            int kc = ks << 3;
            float pe0 = sacc[ks][0], po0 = sacc[ks][1];   // row g   cols 2t4,2t4+1
            float pe1 = sacc[ks][2], po1 = sacc[ks][3];   // row g+8
            float e, o_;
            e  = __shfl_sync(0xffffffffu, pe0, o1lane);
            o_ = __shfl_sync(0xffffffffu, po0, o1lane);
            float a0 = odd ? o_ : e;                      // (g, t4)
            e  = __shfl_sync(0xffffffffu, pe1, o1lane);
            o_ = __shfl_sync(0xffffffffu, po1, o1lane);
            float a1 = odd ? o_ : e;                      // (g+8, t4)
            e  = __shfl_sync(0xffffffffu, pe0, o2lane);
            o_ = __shfl_sync(0xffffffffu, po0, o2lane);
            float a2 = odd ? o_ : e;                      // (g, t4+4)
            e  = __shfl_sync(0xffffffffu, pe1, o2lane);
            o_ = __shfl_sync(0xffffffffu, po1, o2lane);
            float a3 = odd ? o_ : e;                      // (g+8, t4+4)

            uint32_t pah[4] = {__float_as_uint(to_tf32(a0)),
                               __float_as_uint(to_tf32(a1)),
                               __float_as_uint(to_tf32(a2)),
                               __float_as_uint(to_tf32(a3))};
            #pragma unroll
            for (int ni = 0; ni < 8; ni++) {
                int nc = (ni << 3) + g;
                float2 v0 = Vb[(kc + t4)     * PAD2 + nc];
                float2 v1 = Vb[(kc + t4 + 4) * PAD2 + nc];
                uint32_t vh0 = __float_as_uint(v0.x), vh1 = __float_as_uint(v1.x);
                uint32_t vl0 = __float_as_uint(v0.y), vl1 = __float_as_uint(v1.y);
                mma_tf32(oacc[ni], pah[0], pah[1], pah[2], pah[3], vh0, vh1);
                mma_tf32(oacc[ni], pah[0], pah[1], pah[2], pah[3], vl0, vl1);
            }
        }
    }

    // Epilogue: divide by (1 + l), write ctx in [b*l][d] layout
    const int b = bh >> 4, hh = bh & 15;
    #pragma unroll
    for (int hf = 0; hf < 2; hf++) {
        float inv = 1.0f / (1.0f + lrow[hf]);
        int row = q0 + wq + g + (hf << 3);
        #pragma unroll
        for (int ni = 0; ni < 8; ni++) {
            float2 o = { oacc[ni][2*hf] * inv, oacc[ni][2*hf+1] * inv };
            int d = (ni << 3) + (t4 << 1);
            *(float2*)&ctx[((size_t)(b * SEQ + row)) * DIM + hh * HD + d] = o;
        }
    }
}

// ---------------------------------------------------------------------------
extern "C" void kernel_launch(void* const* d_in, const int* in_sizes, int n_in,
                              void* d_out, int out_size)
{
    const float* x  = (const float*)d_in[0];
    const float* Wq = (const float*)d_in[1];
    const float* bq = (const float*)d_in[2];
    const float* Wk = (const float*)d_in[3];
    const float* bk = (const float*)d_in[4];
    const float* Wv = (const float*)d_in[5];
    const float* bv = (const float*)d_in[6];
    const float* Wo = (const float*)d_in[7];
    const float* bo = (const float*)d_in[8];

    float *q, *k, *v, *ctx;
    cudaGetSymbolAddress((void**)&q,   g_q);
    cudaGetSymbolAddress((void**)&k,   g_k);
    cudaGetSymbolAddress((void**)&v,   g_v);
    cudaGetSymbolAddress((void**)&ctx, g_ctx);

    const int attn_smem = 4 * 64 * PAD2 * sizeof(float2);  // 139264
    cudaFuncSetAttribute(attn_mma,
                         cudaFuncAttributeMaxDynamicSharedMemorySize, attn_smem);

    dim3 gg(DIM / 128, MROWS / 128);   // (8, 32)
    gemm_tf32<<<gg, 256>>>(x, Wq, bq, q, 1);
    gemm_tf32<<<gg, 256>>>(x, Wk, bk, k, 1);
    gemm_tf32<<<gg, 256>>>(x, Wv, bv, v, 1);
    attn_mma<<<dim3(SEQ / 128, BATCH * NH), 256, attn_smem>>>(q, k, v, ctx);
    gemm_tf32<<<gg, 256>>>(ctx, Wo, bo, (float*)d_out, 0);
}

// round 15
// speedup vs baseline: 2.6225x; 1.0151x over previous
#include <cuda_runtime.h>
#include <cstdint>

#define DIM 1024
#define NH 16
#define HD 64
#define BATCH 2
#define SEQ 2048
#define MROWS (BATCH*SEQ)   // 4096

// Scratch (allocation-free rule: __device__ globals)
__device__ float  g_q[BATCH*NH*SEQ*HD];     // [b][h][l][hd] fp32
__device__ float2 g_khl[BATCH*NH*SEQ*HD];   // [b][h][l][hd] (hi,lo)
__device__ float2 g_vhl[BATCH*NH*SEQ*HD];   // [b][h][l][hd] (hi,lo)
__device__ float  g_ctx[MROWS*DIM];         // [b*l][d]

__device__ __forceinline__ float to_tf32(float x) {
    float r;
    asm("cvt.rna.tf32.f32 %0, %1;" : "=f"(r) : "f"(x));
    return r;
}

__device__ __forceinline__ void mma_tf32(float d[4],
                                         uint32_t a0, uint32_t a1, uint32_t a2, uint32_t a3,
                                         uint32_t b0, uint32_t b1) {
    asm volatile(
        "mma.sync.aligned.m16n8k8.row.col.f32.tf32.tf32.f32 "
        "{%0,%1,%2,%3}, {%4,%5,%6,%7}, {%8,%9}, {%0,%1,%2,%3};"
        : "+f"(d[0]), "+f"(d[1]), "+f"(d[2]), "+f"(d[3])
        : "r"(a0), "r"(a1), "r"(a2), "r"(a3), "r"(b0), "r"(b1));
}

__device__ __forceinline__ void cp16(void* smem_dst, const void* gmem_src) {
    uint32_t s = (uint32_t)__cvta_generic_to_shared(smem_dst);
    asm volatile("cp.async.cg.shared.global [%0], [%1], 16;"
                 :: "r"(s), "l"(gmem_src));
}
#define CP_COMMIT() asm volatile("cp.async.commit_group;")
#define CP_WAIT0()  asm volatile("cp.async.wait_group 0;")

// ---------------------------------------------------------------------------
// tf32 tensor-core GEMM, double-buffered staging.
// out[M,N] = A[M,K] @ W[K,N] + bias.  BM=BN=128, BK=16, 256 thr, 8 warps.
// mode 0: plain [row][col] fp32.  mode 1: scatter Q [b][h][l][hd] fp32.
// mode 2: scatter K/V [b][h][l][hd] as float2 (tf32-hi, residual-lo).
// ---------------------------------------------------------------------------
#define SST 136
__device__ __forceinline__ void gemm_stage(
    const float* __restrict__ A, const float* __restrict__ W,
    float* As, float* Bs, int m0, int n0, int k0, int t)
{
    #pragma unroll
    for (int i = 0; i < 2; i++) {
        int f = t + (i << 8);
        int r = f >> 2, kc = (f & 3) << 2;
        float4 v = *(const float4*)&A[(size_t)(m0 + r) * DIM + k0 + kc];
        As[(kc + 0) * SST + r] = to_tf32(v.x);
        As[(kc + 1) * SST + r] = to_tf32(v.y);
        As[(kc + 2) * SST + r] = to_tf32(v.z);
        As[(kc + 3) * SST + r] = to_tf32(v.w);
    }
    #pragma unroll
    for (int i = 0; i < 2; i++) {
        int f = t + (i << 8);
        int kr = f >> 5, nc = (f & 31) << 2;
        float4 v = *(const float4*)&W[(size_t)(k0 + kr) * DIM + n0 + nc];
        float4 c;
        c.x = to_tf32(v.x); c.y = to_tf32(v.y);
        c.z = to_tf32(v.z); c.w = to_tf32(v.w);
        *(float4*)&Bs[kr * SST + nc] = c;
    }
}

__global__ __launch_bounds__(256) void gemm_tf32(
    const float* __restrict__ A, const float* __restrict__ W,
    const float* __restrict__ bias, float* __restrict__ out, int mode)
{
    __shared__ float As[2][16 * SST];
    __shared__ float Bs[2][16 * SST];

    const int t    = threadIdx.x;
    const int warp = t >> 5, lane = t & 31;
    const int g  = lane >> 2;
    const int t4 = lane & 3;
    const int wm = (warp >> 2) << 6;
    const int wn = (warp & 3) << 5;
    const int m0 = blockIdx.y << 7, n0 = blockIdx.x << 7;

    float acc[4][4][4];
    #pragma unroll
    for (int mi = 0; mi < 4; mi++)
        #pragma unroll
        for (int ni = 0; ni < 4; ni++)
            #pragma unroll
            for (int e = 0; e < 4; e++) acc[mi][ni][e] = 0.f;

    gemm_stage(A, W, As[0], Bs[0], m0, n0, 0, t);

    int buf = 0;
    for (int k0 = 0; k0 < DIM; k0 += 16) {
        __syncthreads();
        if (k0 + 16 < DIM)
            gemm_stage(A, W, As[buf ^ 1], Bs[buf ^ 1], m0, n0, k0 + 16, t);

        const float* Ab = As[buf];
        const float* Bb = Bs[buf];
        #pragma unroll
        for (int kk = 0; kk < 16; kk += 8) {
            uint32_t aF[4][4], bF[4][2];
            #pragma unroll
            for (int mi = 0; mi < 4; mi++) {
                int m = wm + (mi << 4);
                aF[mi][0] = __float_as_uint(Ab[(kk + t4) * SST + m + g]);
                aF[mi][1] = __float_as_uint(Ab[(kk + t4) * SST + m + g + 8]);
                aF[mi][2] = __float_as_uint(Ab[(kk + t4 + 4) * SST + m + g]);
                aF[mi][3] = __float_as_uint(Ab[(kk + t4 + 4) * SST + m + g + 8]);
            }
            #pragma unroll
            for (int ni = 0; ni < 4; ni++) {
                int n = wn + (ni << 3) + g;
                bF[ni][0] = __float_as_uint(Bb[(kk + t4) * SST + n]);
                bF[ni][1] = __float_as_uint(Bb[(kk + t4 + 4) * SST + n]);
            }
            #pragma unroll
            for (int mi = 0; mi < 4; mi++)
                #pragma unroll
                for (int ni = 0; ni < 4; ni++)
                    mma_tf32(acc[mi][ni], aF[mi][0], aF[mi][1], aF[mi][2], aF[mi][3],
                             bF[ni][0], bF[ni][1]);
        }
        buf ^= 1;
    }

    #pragma unroll
    for (int mi = 0; mi < 4; mi++) {
        #pragma unroll
        for (int ni = 0; ni < 4; ni++) {
            int r0 = m0 + wm + (mi << 4) + g;
            int c0 = n0 + wn + (ni << 3) + (t4 << 1);
            float bx = bias[c0], by = bias[c0 + 1];
            #pragma unroll
            for (int half = 0; half < 2; half++) {
                int row = r0 + (half << 3);
                float ox = acc[mi][ni][half * 2 + 0] + bx;
                float oy = acc[mi][ni][half * 2 + 1] + by;
                if (mode == 0) {
                    float2 o = {ox, oy};
                    *(float2*)&out[(size_t)row * DIM + c0] = o;
                } else {
                    int b = row >> 11, l = row & 2047;
                    int h = c0 >> 6, dd = c0 & 63;
                    size_t idx = ((size_t)((b * NH + h) * SEQ) + l) * HD + dd;
                    if (mode == 1) {
                        float2 o = {ox, oy};
                        *(float2*)&out[idx] = o;
                    } else {
                        float hx = to_tf32(ox), hy = to_tf32(oy);
                        float4 st = {hx, to_tf32(ox - hx), hy, to_tf32(oy - hy)};
                        *(float4*)&((float2*)out)[idx] = st;
                    }
                }
            }
        }
    }
}

// ---------------------------------------------------------------------------
// Flash attention on tensor cores.
// S = QK^T in 3xTF32; PV = P_hi * (V_hi + V_lo).
// R13: K/V are pre-split (hi,lo) in gmem by the projection GEMMs; staging is
// pure cp.async.cg 16B copies into the padded smem layout -> no cvt, no
// register staging, fully async double-buffered prefetch. exp2 softmax,
// quad-shuffle P transpose. BQ=128, BK=64, 8 warps.
// ---------------------------------------------------------------------------
#define PAD2 68   // float2 row stride (=136 words, ≡8 mod 32 -> conflict-free)
#define SCALE2 0.1803368801111204f   // 0.125 * log2(e)

__device__ __forceinline__ void attn_stage_async(
    const float2* __restrict__ Kg, const float2* __restrict__ Vg,
    float2* Kb, float2* Vb, int k0, int t)
{
    #pragma unroll
    for (int i = 0; i < 8; i++) {
        int f = t + (i << 8);            // 0..2047
        int r = f >> 5;                  // key row 0..63
        int c = (f & 31) << 1;           // float2 col (even): covers c, c+1
        cp16(&Kb[r * PAD2 + c], &Kg[(size_t)(k0 + r) * HD + c]);
        cp16(&Vb[r * PAD2 + c], &Vg[(size_t)(k0 + r) * HD + c]);
    }
}

__global__ __launch_bounds__(256, 1) void attn_mma(
    const float* __restrict__ gq, const float2* __restrict__ gkhl,
    const float2* __restrict__ gvhl, float* __restrict__ ctx)
{
    extern __shared__ float2 sm2[];
    float2* Kbuf[2] = { sm2,             sm2 + 64 * PAD2 };
    float2* Vbuf[2] = { sm2 + 2*64*PAD2, sm2 + 3*64*PAD2 };

    const int t    = threadIdx.x;
    const int warp = t >> 5, lane = t & 31;
    const int g  = lane >> 2;
    const int t4 = lane & 3;
    const int wq = warp << 4;
    const int qb = (int)gridDim.x - 1 - (int)blockIdx.x;  // heavy tiles first
    const int q0 = qb << 7;
    const int bh = blockIdx.y;

    const float*  Q  = gq   + (size_t)bh * SEQ * HD;
    const float2* Kg = gkhl + (size_t)bh * SEQ * HD;
    const float2* Vg = gvhl + (size_t)bh * SEQ * HD;

    const int ktmax = (qb << 1) + 1;

    // Kick off tile 0 staging before anything else
    attn_stage_async(Kg, Vg, Kbuf[0], Vbuf[0], 0, t);
    CP_COMMIT();

    // Pre-split Q fragments for all 8 k-steps (overlaps with cp.async)
    uint32_t qh[8][4], ql[8][4];
    #pragma unroll
    for (int ks = 0; ks < 8; ks++) {
        #pragma unroll
        for (int e = 0; e < 4; e++) {
            int row = q0 + wq + g + ((e & 1) << 3);
            int col = (ks << 3) + t4 + ((e >> 1) << 2);
            float v = Q[(size_t)row * HD + col];
            float h = to_tf32(v);
            qh[ks][e] = __float_as_uint(h);
            ql[ks][e] = __float_as_uint(to_tf32(v - h));
        }
    }

    float oacc[8][4];
    #pragma unroll
    for (int ni = 0; ni < 8; ni++)
        #pragma unroll
        for (int e = 0; e < 4; e++) oacc[ni][e] = 0.f;
    float mrow[2] = {-1e30f, -1e30f};   // base-2 domain
    float lrow[2] = {0.f, 0.f};

    const int o1lane = (lane & 28) | (t4 >> 1);   // owner of col t4
    const int o2lane = o1lane + 2;                // owner of col t4+4
    const bool odd = (t4 & 1);

    for (int kt = 0; kt <= ktmax; kt++) {
        const int k0 = kt << 6;
        const float2* Kb = Kbuf[kt & 1];
        const float2* Vb = Vbuf[kt & 1];

        CP_WAIT0();        // tile kt landed in smem
        __syncthreads();   // all warps done reading the buffer we overwrite next

        // Prefetch tile kt+1 (fully async behind this tile's compute)
        if (kt < ktmax) {
            attn_stage_async(Kg, Vg, Kbuf[(kt + 1) & 1], Vbuf[(kt + 1) & 1],
                             (kt + 1) << 6, t);
            CP_COMMIT();
        }

        // ---- S = Q K^T (3xTF32) ----
        float sacc[8][4];
        #pragma unroll
        for (int ni = 0; ni < 8; ni++)
            #pragma unroll
            for (int e = 0; e < 4; e++) sacc[ni][e] = 0.f;

        #pragma unroll
        for (int ks = 0; ks < 8; ks++) {
            int kc = ks << 3;
            #pragma unroll
            for (int ni = 0; ni < 8; ni++) {
                int nrow = (ni << 3) + g;
                float2 kv0 = Kb[nrow * PAD2 + kc + t4];
                float2 kv1 = Kb[nrow * PAD2 + kc + t4 + 4];
                uint32_t kh0 = __float_as_uint(kv0.x), kh1 = __float_as_uint(kv1.x);
                uint32_t kl0 = __float_as_uint(kv0.y), kl1 = __float_as_uint(kv1.y);
                mma_tf32(sacc[ni], qh[ks][0], qh[ks][1], qh[ks][2], qh[ks][3], kh0, kh1);
                mma_tf32(sacc[ni], qh[ks][0], qh[ks][1], qh[ks][2], qh[ks][3], kl0, kl1);
                mma_tf32(sacc[ni], ql[ks][0], ql[ks][1], ql[ks][2], ql[ks][3], kh0, kh1);
            }
        }

        // ---- scale to base-2 domain + causal mask (boundary tiles) ----
        const bool need_mask = (kt >= ktmax - 1);
        #pragma unroll
        for (int ni = 0; ni < 8; ni++)
            #pragma unroll
            for (int e = 0; e < 4; e++) {
                float s = sacc[ni][e] * SCALE2;
                if (need_mask) {
                    int row = q0 + wq + g + ((e >> 1) << 3);
                    int col = k0 + (ni << 3) + (t4 << 1) + (e & 1);
                    if (col > row) s = -1e30f;
                }
                sacc[ni][e] = s;
            }

        // ---- online quiet softmax (exp2 domain) ----
        #pragma unroll
        for (int hf = 0; hf < 2; hf++) {
            float rm = -1e30f;
            #pragma unroll
            for (int ni = 0; ni < 8; ni++)
                rm = fmaxf(rm, fmaxf(sacc[ni][2*hf], sacc[ni][2*hf+1]));
            rm = fmaxf(rm, __shfl_xor_sync(0xffffffffu, rm, 1));
            rm = fmaxf(rm, __shfl_xor_sync(0xffffffffu, rm, 2));
            float mn = fmaxf(mrow[hf], rm);
            float al = exp2f(mrow[hf] - mn);
            float ls = 0.f;
            #pragma unroll
            for (int ni = 0; ni < 8; ni++) {
                float p0 = exp2f(sacc[ni][2*hf]   - mn);
                float p1 = exp2f(sacc[ni][2*hf+1] - mn);
                sacc[ni][2*hf]   = p0;
                sacc[ni][2*hf+1] = p1;
                ls += p0 + p1;
            }
            ls += __shfl_xor_sync(0xffffffffu, ls, 1);
            ls += __shfl_xor_sync(0xffffffffu, ls, 2);
            lrow[hf] = lrow[hf] * al + ls;
            mrow[hf] = mn;
            #pragma unroll
            for (int ni = 0; ni < 8; ni++) {
                oacc[ni][2*hf]   *= al;
                oacc[ni][2*hf+1] *= al;
            }
        }

        // ---- O += P_hi * V (2-term). P C->A layout via exact quad shuffles.
        #pragma unroll
        for (int ks = 0; ks < 8; ks++) {
            int kc = ks << 3;
            float pe0 = sacc[ks][0], po0 = sacc[ks][1];   // row g   cols 2t4,2t4+1
            float pe1 = sacc[ks][2], po1 = sacc[ks][3];   // row g+8
            float e, o_;
            e  = __shfl_sync(0xffffffffu, pe0, o1lane);
            o_ = __shfl_sync(0xffffffffu, po0, o1lane);
            float a0 = odd ? o_ : e;                      // (g, t4)
            e  = __shfl_sync(0xffffffffu, pe1, o1lane);
            o_ = __shfl_sync(0xffffffffu, po1, o1lane);
            float a1 = odd ? o_ : e;                      // (g+8, t4)
            e  = __shfl_sync(0xffffffffu, pe0, o2lane);
            o_ = __shfl_sync(0xffffffffu, po0, o2lane);
            float a2 = odd ? o_ : e;                      // (g, t4+4)
            e  = __shfl_sync(0xffffffffu, pe1, o2lane);
            o_ = __shfl_sync(0xffffffffu, po1, o2lane);
            float a3 = odd ? o_ : e;                      // (g+8, t4+4)

            uint32_t pah[4] = {__float_as_uint(to_tf32(a0)),
                               __float_as_uint(to_tf32(a1)),
                               __float_as_uint(to_tf32(a2)),
                               __float_as_uint(to_tf32(a3))};
            #pragma unroll
            for (int ni = 0; ni < 8; ni++) {
                int nc = (ni << 3) + g;
                float2 v0 = Vb[(kc + t4)     * PAD2 + nc];
                float2 v1 = Vb[(kc + t4 + 4) * PAD2 + nc];
                uint32_t vh0 = __float_as_uint(v0.x), vh1 = __float_as_uint(v1.x);
                uint32_t vl0 = __float_as_uint(v0.y), vl1 = __float_as_uint(v1.y);
                mma_tf32(oacc[ni], pah[0], pah[1], pah[2], pah[3], vh0, vh1);
                mma_tf32(oacc[ni], pah[0], pah[1], pah[2], pah[3], vl0, vl1);
            }
        }
    }

    // Epilogue: divide by (1 + l), write ctx in [b*l][d] layout
    const int b = bh >> 4, hh = bh & 15;
    #pragma unroll
    for (int hf = 0; hf < 2; hf++) {
        float inv = 1.0f / (1.0f + lrow[hf]);
        int row = q0 + wq + g + (hf << 3);
        #pragma unroll
        for (int ni = 0; ni < 8; ni++) {
            float2 o = { oacc[ni][2*hf] * inv, oacc[ni][2*hf+1] * inv };
            int d = (ni << 3) + (t4 << 1);
            *(float2*)&ctx[((size_t)(b * SEQ + row)) * DIM + hh * HD + d] = o;
        }
    }
}

// ---------------------------------------------------------------------------
extern "C" void kernel_launch(void* const* d_in, const int* in_sizes, int n_in,
                              void* d_out, int out_size)
{
    const float* x  = (const float*)d_in[0];
    const float* Wq = (const float*)d_in[1];
    const float* bq = (const float*)d_in[2];
    const float* Wk = (const float*)d_in[3];
    const float* bk = (const float*)d_in[4];
    const float* Wv = (const float*)d_in[5];
    const float* bv = (const float*)d_in[6];
    const float* Wo = (const float*)d_in[7];
    const float* bo = (const float*)d_in[8];

    float *q, *ctx;
    float2 *khl, *vhl;
    cudaGetSymbolAddress((void**)&q,   g_q);
    cudaGetSymbolAddress((void**)&khl, g_khl);
    cudaGetSymbolAddress((void**)&vhl, g_vhl);
    cudaGetSymbolAddress((void**)&ctx, g_ctx);

    const int attn_smem = 4 * 64 * PAD2 * sizeof(float2);  // 139264
    cudaFuncSetAttribute(attn_mma,
                         cudaFuncAttributeMaxDynamicSharedMemorySize, attn_smem);

    dim3 gg(DIM / 128, MROWS / 128);   // (8, 32)
    gemm_tf32<<<gg, 256>>>(x, Wq, bq, q, 1);
    gemm_tf32<<<gg, 256>>>(x, Wk, bk, (float*)khl, 2);
    gemm_tf32<<<gg, 256>>>(x, Wv, bv, (float*)vhl, 2);
    attn_mma<<<dim3(SEQ / 128, BATCH * NH), 256, attn_smem>>>(q, khl, vhl, ctx);
    gemm_tf32<<<gg, 256>>>(ctx, Wo, bo, (float*)d_out, 0);
}